// round 6
// baseline (speedup 1.0000x reference)
#include <cuda_runtime.h>
#include <math.h>

#define D_MODEL 1024
#define D_STATE 16
#define D_CONV  4
#define D_INNER 2048
#define DT_RANK 64
#define NBLK    4
#define BATCH   2
#define SEQLEN  1024
#define M_TOK   (BATCH*SEQLEN)   // 2048 tokens
#define XD      96               // dt_rank + 2*d_state

// ---------------- scratch (no allocation allowed) ----------------
__device__ __align__(256) float g_h[M_TOK*D_MODEL];            // 8 MB
__device__ __align__(256) float g_xz[(size_t)M_TOK*2*D_INNER]; // 32 MB
__device__ __align__(256) float g_u[(size_t)M_TOK*D_INNER];    // 16 MB
__device__ __align__(256) float g_xdbl[M_TOK*XD];
__device__ __align__(256) float g_xdbl_part[4*M_TOK*XD];
__device__ __align__(256) float g_dt[(size_t)M_TOK*D_INNER];   // 16 MB
__device__ __align__(256) float g_yg[(size_t)M_TOK*D_INNER];   // 16 MB

__device__ __forceinline__ float siluf(float v) {
    return v / (1.f + __expf(-v));
}

// ---------------- generic fp32 SGEMM:  C[M,N] = A[M,K(lda)] * W[N,K]^T ----------------
// EPI: 0 = none, 1 = softplus(x + bias[n]), 2 = silu
// SPLIT: grid.z splits K; each split writes its own partial buffer slice.
template<int BM,int BN,int BK,int TM,int TN,int EPI,bool SPLIT>
__global__ void __launch_bounds__((BM/TM)*(BN/TN), 2) sgemm_k(
    const float* __restrict__ A, const float* __restrict__ W,
    const float* __restrict__ bias, float* __restrict__ C,
    int M, int N, int K, int lda, int ksplit)
{
    constexpr int THREADS = (BM/TM)*(BN/TN);
    __shared__ float As[BK][BM];
    __shared__ float Bs[BK][BN];

    const int bm = blockIdx.y * BM;
    const int bn = blockIdx.x * BN;
    int k0 = 0, kend = K;
    if (SPLIT) {
        k0 = blockIdx.z * ksplit;
        kend = k0 + ksplit;
        C += (size_t)blockIdx.z * (size_t)M * N;
    }

    const int tid = threadIdx.x;
    const int tx = tid % (BN/TN);
    const int ty = tid / (BN/TN);

    float acc[TM][TN];
#pragma unroll
    for (int i = 0; i < TM; i++)
#pragma unroll
        for (int j = 0; j < TN; j++) acc[i][j] = 0.f;

    for (int kt = k0; kt < kend; kt += BK) {
        // load A tile (BM x BK), transpose into As[k][m]
#pragma unroll
        for (int idx = tid; idx < BM*(BK/4); idx += THREADS) {
            int row = idx / (BK/4), kq = idx % (BK/4);
            float4 v = *reinterpret_cast<const float4*>(A + (size_t)(bm+row)*lda + kt + kq*4);
            As[kq*4+0][row] = v.x; As[kq*4+1][row] = v.y;
            As[kq*4+2][row] = v.z; As[kq*4+3][row] = v.w;
        }
        // load W tile (BN x BK), transpose into Bs[k][n]
#pragma unroll
        for (int idx = tid; idx < BN*(BK/4); idx += THREADS) {
            int col = idx / (BK/4), kq = idx % (BK/4);
            float4 v = *reinterpret_cast<const float4*>(W + (size_t)(bn+col)*K + kt + kq*4);
            Bs[kq*4+0][col] = v.x; Bs[kq*4+1][col] = v.y;
            Bs[kq*4+2][col] = v.z; Bs[kq*4+3][col] = v.w;
        }
        __syncthreads();
#pragma unroll
        for (int k = 0; k < BK; k++) {
            float a[TM], b[TN];
#pragma unroll
            for (int i = 0; i < TM; i++) a[i] = As[k][ty*TM + i];
#pragma unroll
            for (int j = 0; j < TN; j++) b[j] = Bs[k][tx*TN + j];
#pragma unroll
            for (int i = 0; i < TM; i++)
#pragma unroll
                for (int j = 0; j < TN; j++)
                    acc[i][j] = fmaf(a[i], b[j], acc[i][j]);
        }
        __syncthreads();
    }

#pragma unroll
    for (int i = 0; i < TM; i++) {
        int m = bm + ty*TM + i;
#pragma unroll
        for (int j = 0; j < TN; j++) {
            int n = bn + tx*TN + j;
            float v = acc[i][j];
            if (EPI == 1) {                       // softplus(x + bias)
                v += bias[n];
                v = fmaxf(v, 0.f) + log1pf(__expf(-fabsf(v)));
            }
            if (EPI == 2) {                       // silu
                v = siluf(v);
            }
            C[(size_t)m * N + n] = v;
        }
    }
}

// ---------------- embedding: h[m,d] = x[m]*emb_w[d] + emb_b[d] ----------------
__global__ void embed_k(const float* __restrict__ x, const float* __restrict__ ew,
                        const float* __restrict__ eb, float* __restrict__ h)
{
    int i = blockIdx.x * blockDim.x + threadIdx.x;  // M_TOK*D_MODEL
    int d = i % D_MODEL, m = i / D_MODEL;
    h[i] = fmaf(x[m], ew[d], eb[d]);
}

// ---------------- causal depthwise conv (width 4) + silu ----------------
__global__ void conv_silu_k(const float* __restrict__ xz, const float* __restrict__ cw,
                            const float* __restrict__ cb, float* __restrict__ u)
{
    int i = blockIdx.x * blockDim.x + threadIdx.x;  // M_TOK*D_INNER
    int d = i % D_INNER;
    int m = i / D_INNER;
    int t = m % SEQLEN;
    float acc = cb[d];
#pragma unroll
    for (int k = 0; k < D_CONV; k++) {
        int tt = t - (D_CONV-1) + k;
        if (tt >= 0)
            acc = fmaf(cw[d*D_CONV + k], xz[(size_t)(m-(D_CONV-1)+k)*(2*D_INNER) + d], acc);
    }
    u[i] = siluf(acc);
}

// ---------------- reduce split-K partials ----------------
__global__ void reduce4_k(float* __restrict__ out, const float* __restrict__ part, int n)
{
    int i = blockIdx.x * blockDim.x + threadIdx.x;
    if (i < n)
        out[i] = (part[i] + part[n + i]) + (part[2*n + i] + part[3*n + i]);
}

// ---------------- selective scan + gating fused ----------------
// block: 512 threads = 32 d-channels x 16 states; grid (D_INNER/32, BATCH)
#define SC_D 32
#define SC_T 64
__global__ void __launch_bounds__(512) scan_k(
    const float* __restrict__ dt, const float* __restrict__ u,
    const float* __restrict__ xdbl, const float* __restrict__ xz,
    const float* __restrict__ A_log, const float* __restrict__ Dp,
    float* __restrict__ yg)
{
    __shared__ float s_dt[SC_T][SC_D];
    __shared__ float s_u [SC_T][SC_D];
    __shared__ float s_z [SC_T][SC_D];
    __shared__ float s_B [SC_T][D_STATE];
    __shared__ float s_C [SC_T][D_STATE];

    const int b  = blockIdx.y;
    const int d0 = blockIdx.x * SC_D;
    const int tid = threadIdx.x;
    const int n  = tid & 15;
    const int dl = tid >> 4;
    const int d  = d0 + dl;

    const float Aval = -__expf(A_log[d*D_STATE + n]);
    const float Dval = Dp[d];
    float s = 0.f;
    const size_t rowbase = (size_t)b * SEQLEN;

    for (int t0 = 0; t0 < SEQLEN; t0 += SC_T) {
        for (int idx = tid; idx < SC_T*SC_D; idx += 512) {
            int tl = idx / SC_D, dd = idx % SC_D;
            size_t r = rowbase + t0 + tl;
            s_dt[tl][dd] = dt[r*D_INNER + d0 + dd];
            s_u [tl][dd] = u [r*D_INNER + d0 + dd];
            s_z [tl][dd] = xz[r*(2*D_INNER) + D_INNER + d0 + dd];
        }
        for (int idx = tid; idx < SC_T*D_STATE; idx += 512) {
            int tl = idx / D_STATE, nn = idx % D_STATE;
            size_t r = rowbase + t0 + tl;
            s_B[tl][nn] = xdbl[r*XD + DT_RANK + nn];
            s_C[tl][nn] = xdbl[r*XD + DT_RANK + D_STATE + nn];
        }
        __syncthreads();

        for (int tl = 0; tl < SC_T; tl++) {
            float dtv = s_dt[tl][dl];
            float uv  = s_u [tl][dl];
            float dA  = __expf(dtv * Aval);
            s = fmaf(dA, s, dtv * uv * s_B[tl][n]);
            float y = s * s_C[tl][n];
#pragma unroll
            for (int off = 8; off; off >>= 1)
                y += __shfl_xor_sync(0xffffffffu, y, off, 16);
            if (n == 0) {
                float zv = s_z[tl][dl];
                float yy = fmaf(Dval, uv, y);
                yg[(rowbase + t0 + tl)*D_INNER + d] = yy * siluf(zv);
            }
        }
        __syncthreads();
    }
}

// ---------------- host ----------------
extern "C" void kernel_launch(void* const* d_in, const int* in_sizes, int n_in,
                              void* d_out, int out_size)
{
    const float* x          = (const float*)d_in[0];
    const float* emb_w      = (const float*)d_in[1];
    const float* emb_b      = (const float*)d_in[2];
    const float* in_proj_w  = (const float*)d_in[3];
    const float* conv_w     = (const float*)d_in[4];
    const float* conv_b     = (const float*)d_in[5];
    const float* x_proj_w   = (const float*)d_in[6];
    const float* dt_proj_w  = (const float*)d_in[7];
    const float* dt_proj_b  = (const float*)d_in[8];
    const float* A_log      = (const float*)d_in[9];
    const float* D_param    = (const float*)d_in[10];
    const float* out_proj_w = (const float*)d_in[11];
    float* out = (float*)d_out;

    float *ph, *pxz, *pu, *pxdbl, *pxpart, *pdt, *pyg;
    cudaGetSymbolAddress((void**)&ph,     g_h);
    cudaGetSymbolAddress((void**)&pxz,    g_xz);
    cudaGetSymbolAddress((void**)&pu,     g_u);
    cudaGetSymbolAddress((void**)&pxdbl,  g_xdbl);
    cudaGetSymbolAddress((void**)&pxpart, g_xdbl_part);
    cudaGetSymbolAddress((void**)&pdt,    g_dt);
    cudaGetSymbolAddress((void**)&pyg,    g_yg);

    embed_k<<<(M_TOK*D_MODEL)/256, 256>>>(x, emb_w, emb_b, ph);

    for (int i = 0; i < NBLK; i++) {
        float* h_out = (i == NBLK-1) ? out : ph;

        // GEMM1: xz = h @ in_proj_w^T   [2048 x 4096 x 1024]
        sgemm_k<128,128,16,8,8,0,false>
            <<<dim3((2*D_INNER)/128, M_TOK/128), 256>>>(
                ph, in_proj_w + (size_t)i*2*D_INNER*D_MODEL, nullptr, pxz,
                M_TOK, 2*D_INNER, D_MODEL, D_MODEL, 0);

        // depthwise conv + silu -> u
        conv_silu_k<<<(M_TOK*D_INNER)/256, 256>>>(
            pxz, conv_w + (size_t)i*D_INNER*D_CONV, conv_b + (size_t)i*D_INNER, pu);

        // GEMM2 (split-K x4): x_dbl partials = u @ x_proj_w^T   [2048 x 96 x 2048]
        sgemm_k<64,96,16,4,6,0,true>
            <<<dim3(1, M_TOK/64, 4), 256>>>(
                pu, x_proj_w + (size_t)i*XD*D_INNER, nullptr, pxpart,
                M_TOK, XD, D_INNER, D_INNER, D_INNER/4);
        reduce4_k<<<(M_TOK*XD + 255)/256, 256>>>(pxdbl, pxpart, M_TOK*XD);

        // GEMM3: dt = softplus(dt_lo @ dt_proj_w^T + b)   [2048 x 2048 x 64], lda=96
        sgemm_k<128,128,16,8,8,1,false>
            <<<dim3(D_INNER/128, M_TOK/128), 256>>>(
                pxdbl, dt_proj_w + (size_t)i*D_INNER*DT_RANK,
                dt_proj_b + (size_t)i*D_INNER, pdt,
                M_TOK, D_INNER, DT_RANK, XD, 0);

        // selective scan + (y + D*u)*silu(z) fused -> yg
        scan_k<<<dim3(D_INNER/SC_D, BATCH), 512>>>(
            pdt, pu, pxdbl, pxz,
            A_log + (size_t)i*D_INNER*D_STATE, D_param + (size_t)i*D_INNER, pyg);

        // GEMM4: h' = silu(yg @ out_proj_w^T)   [2048 x 1024 x 2048]
        sgemm_k<128,128,16,8,8,2,false>
            <<<dim3(D_MODEL/128, M_TOK/128), 256>>>(
                pyg, out_proj_w + (size_t)i*D_MODEL*D_INNER, nullptr, h_out,
                M_TOK, D_MODEL, D_INNER, D_INNER, 0);
    }
    (void)in_sizes; (void)n_in; (void)out_size;
}

// round 7
// speedup vs baseline: 1.0007x; 1.0007x over previous
#include <cuda_runtime.h>
#include <math.h>

#define D_MODEL 1024
#define D_STATE 16
#define D_CONV  4
#define D_INNER 2048
#define DT_RANK 64
#define NBLK    4
#define BATCH   2
#define SEQLEN  1024
#define M_TOK   (BATCH*SEQLEN)   // 2048 tokens
#define XD      96               // dt_rank + 2*d_state

// ---------------- scratch (no allocation allowed) ----------------
__device__ __align__(256) float g_h[M_TOK*D_MODEL];            // 8 MB
__device__ __align__(256) float g_xz[(size_t)M_TOK*2*D_INNER]; // 32 MB
__device__ __align__(256) float g_u[(size_t)M_TOK*D_INNER];    // 16 MB
__device__ __align__(256) float g_xdbl[M_TOK*XD];
__device__ __align__(256) float g_xdbl_part[4*M_TOK*XD];
__device__ __align__(256) float g_dt[(size_t)M_TOK*D_INNER];   // 16 MB
__device__ __align__(256) float g_yg[(size_t)M_TOK*D_INNER];   // 16 MB

__device__ __forceinline__ float siluf(float v) {
    return v / (1.f + __expf(-v));
}

// ---------------- generic fp32 SGEMM:  C[M,N] = A[M,K(lda)] * W[N,K]^T ----------------
// EPI: 0 = none, 1 = softplus(x + bias[n]), 2 = silu
// SPLIT: grid.z splits K; each split writes its own partial buffer slice.
template<int BM,int BN,int BK,int TM,int TN,int EPI,bool SPLIT>
__global__ void __launch_bounds__((BM/TM)*(BN/TN), 2) sgemm_k(
    const float* __restrict__ A, const float* __restrict__ W,
    const float* __restrict__ bias, float* __restrict__ C,
    int M, int N, int K, int lda, int ksplit)
{
    constexpr int THREADS = (BM/TM)*(BN/TN);
    __shared__ float As[BK][BM];
    __shared__ float Bs[BK][BN];

    const int bm = blockIdx.y * BM;
    const int bn = blockIdx.x * BN;
    int k0 = 0, kend = K;
    if (SPLIT) {
        k0 = blockIdx.z * ksplit;
        kend = k0 + ksplit;
        C += (size_t)blockIdx.z * (size_t)M * N;
    }

    const int tid = threadIdx.x;
    const int tx = tid % (BN/TN);
    const int ty = tid / (BN/TN);

    float acc[TM][TN];
#pragma unroll
    for (int i = 0; i < TM; i++)
#pragma unroll
        for (int j = 0; j < TN; j++) acc[i][j] = 0.f;

    for (int kt = k0; kt < kend; kt += BK) {
        // load A tile (BM x BK), transpose into As[k][m]
#pragma unroll
        for (int idx = tid; idx < BM*(BK/4); idx += THREADS) {
            int row = idx / (BK/4), kq = idx % (BK/4);
            float4 v = *reinterpret_cast<const float4*>(A + (size_t)(bm+row)*lda + kt + kq*4);
            As[kq*4+0][row] = v.x; As[kq*4+1][row] = v.y;
            As[kq*4+2][row] = v.z; As[kq*4+3][row] = v.w;
        }
        // load W tile (BN x BK), transpose into Bs[k][n]
#pragma unroll
        for (int idx = tid; idx < BN*(BK/4); idx += THREADS) {
            int col = idx / (BK/4), kq = idx % (BK/4);
            float4 v = *reinterpret_cast<const float4*>(W + (size_t)(bn+col)*K + kt + kq*4);
            Bs[kq*4+0][col] = v.x; Bs[kq*4+1][col] = v.y;
            Bs[kq*4+2][col] = v.z; Bs[kq*4+3][col] = v.w;
        }
        __syncthreads();
#pragma unroll
        for (int k = 0; k < BK; k++) {
            float a[TM], b[TN];
#pragma unroll
            for (int i = 0; i < TM; i++) a[i] = As[k][ty*TM + i];
#pragma unroll
            for (int j = 0; j < TN; j++) b[j] = Bs[k][tx*TN + j];
#pragma unroll
            for (int i = 0; i < TM; i++)
#pragma unroll
                for (int j = 0; j < TN; j++)
                    acc[i][j] = fmaf(a[i], b[j], acc[i][j]);
        }
        __syncthreads();
    }

#pragma unroll
    for (int i = 0; i < TM; i++) {
        int m = bm + ty*TM + i;
#pragma unroll
        for (int j = 0; j < TN; j++) {
            int n = bn + tx*TN + j;
            float v = acc[i][j];
            if (EPI == 1) {                       // softplus(x + bias)
                v += bias[n];
                v = fmaxf(v, 0.f) + log1pf(__expf(-fabsf(v)));
            }
            if (EPI == 2) {                       // silu
                v = siluf(v);
            }
            C[(size_t)m * N + n] = v;
        }
    }
}

// ---------------- embedding: h[m,d] = x[m]*emb_w[d] + emb_b[d] ----------------
__global__ void embed_k(const float* __restrict__ x, const float* __restrict__ ew,
                        const float* __restrict__ eb, float* __restrict__ h)
{
    int i = blockIdx.x * blockDim.x + threadIdx.x;  // M_TOK*D_MODEL
    int d = i % D_MODEL, m = i / D_MODEL;
    h[i] = fmaf(x[m], ew[d], eb[d]);
}

// ---------------- causal depthwise conv (width 4) + silu ----------------
__global__ void conv_silu_k(const float* __restrict__ xz, const float* __restrict__ cw,
                            const float* __restrict__ cb, float* __restrict__ u)
{
    int i = blockIdx.x * blockDim.x + threadIdx.x;  // M_TOK*D_INNER
    int d = i % D_INNER;
    int m = i / D_INNER;
    int t = m % SEQLEN;
    float acc = cb[d];
#pragma unroll
    for (int k = 0; k < D_CONV; k++) {
        int tt = t - (D_CONV-1) + k;
        if (tt >= 0)
            acc = fmaf(cw[d*D_CONV + k], xz[(size_t)(m-(D_CONV-1)+k)*(2*D_INNER) + d], acc);
    }
    u[i] = siluf(acc);
}

// ---------------- reduce split-K partials ----------------
__global__ void reduce4_k(float* __restrict__ out, const float* __restrict__ part, int n)
{
    int i = blockIdx.x * blockDim.x + threadIdx.x;
    if (i < n)
        out[i] = (part[i] + part[n + i]) + (part[2*n + i] + part[3*n + i]);
}

// ---------------- selective scan + gating fused ----------------
// block: 512 threads = 32 d-channels x 16 states; grid (D_INNER/32, BATCH)
#define SC_D 32
#define SC_T 64
__global__ void __launch_bounds__(512) scan_k(
    const float* __restrict__ dt, const float* __restrict__ u,
    const float* __restrict__ xdbl, const float* __restrict__ xz,
    const float* __restrict__ A_log, const float* __restrict__ Dp,
    float* __restrict__ yg)
{
    __shared__ float s_dt[SC_T][SC_D];
    __shared__ float s_u [SC_T][SC_D];
    __shared__ float s_z [SC_T][SC_D];
    __shared__ float s_B [SC_T][D_STATE];
    __shared__ float s_C [SC_T][D_STATE];

    const int b  = blockIdx.y;
    const int d0 = blockIdx.x * SC_D;
    const int tid = threadIdx.x;
    const int n  = tid & 15;
    const int dl = tid >> 4;
    const int d  = d0 + dl;

    const float Aval = -__expf(A_log[d*D_STATE + n]);
    const float Dval = Dp[d];
    float s = 0.f;
    const size_t rowbase = (size_t)b * SEQLEN;

    for (int t0 = 0; t0 < SEQLEN; t0 += SC_T) {
        for (int idx = tid; idx < SC_T*SC_D; idx += 512) {
            int tl = idx / SC_D, dd = idx % SC_D;
            size_t r = rowbase + t0 + tl;
            s_dt[tl][dd] = dt[r*D_INNER + d0 + dd];
            s_u [tl][dd] = u [r*D_INNER + d0 + dd];
            s_z [tl][dd] = xz[r*(2*D_INNER) + D_INNER + d0 + dd];
        }
        for (int idx = tid; idx < SC_T*D_STATE; idx += 512) {
            int tl = idx / D_STATE, nn = idx % D_STATE;
            size_t r = rowbase + t0 + tl;
            s_B[tl][nn] = xdbl[r*XD + DT_RANK + nn];
            s_C[tl][nn] = xdbl[r*XD + DT_RANK + D_STATE + nn];
        }
        __syncthreads();

        for (int tl = 0; tl < SC_T; tl++) {
            float dtv = s_dt[tl][dl];
            float uv  = s_u [tl][dl];
            float dA  = __expf(dtv * Aval);
            s = fmaf(dA, s, dtv * uv * s_B[tl][n]);
            float y = s * s_C[tl][n];
#pragma unroll
            for (int off = 8; off; off >>= 1)
                y += __shfl_xor_sync(0xffffffffu, y, off, 16);
            if (n == 0) {
                float zv = s_z[tl][dl];
                float yy = fmaf(Dval, uv, y);
                yg[(rowbase + t0 + tl)*D_INNER + d] = yy * siluf(zv);
            }
        }
        __syncthreads();
    }
}

// ---------------- host ----------------
extern "C" void kernel_launch(void* const* d_in, const int* in_sizes, int n_in,
                              void* d_out, int out_size)
{
    const float* x          = (const float*)d_in[0];
    const float* emb_w      = (const float*)d_in[1];
    const float* emb_b      = (const float*)d_in[2];
    const float* in_proj_w  = (const float*)d_in[3];
    const float* conv_w     = (const float*)d_in[4];
    const float* conv_b     = (const float*)d_in[5];
    const float* x_proj_w   = (const float*)d_in[6];
    const float* dt_proj_w  = (const float*)d_in[7];
    const float* dt_proj_b  = (const float*)d_in[8];
    const float* A_log      = (const float*)d_in[9];
    const float* D_param    = (const float*)d_in[10];
    const float* out_proj_w = (const float*)d_in[11];
    float* out = (float*)d_out;

    float *ph, *pxz, *pu, *pxdbl, *pxpart, *pdt, *pyg;
    cudaGetSymbolAddress((void**)&ph,     g_h);
    cudaGetSymbolAddress((void**)&pxz,    g_xz);
    cudaGetSymbolAddress((void**)&pu,     g_u);
    cudaGetSymbolAddress((void**)&pxdbl,  g_xdbl);
    cudaGetSymbolAddress((void**)&pxpart, g_xdbl_part);
    cudaGetSymbolAddress((void**)&pdt,    g_dt);
    cudaGetSymbolAddress((void**)&pyg,    g_yg);

    embed_k<<<(M_TOK*D_MODEL)/256, 256>>>(x, emb_w, emb_b, ph);

    for (int i = 0; i < NBLK; i++) {
        float* h_out = (i == NBLK-1) ? out : ph;

        // GEMM1: xz = h @ in_proj_w^T   [2048 x 4096 x 1024]
        sgemm_k<128,128,16,8,8,0,false>
            <<<dim3((2*D_INNER)/128, M_TOK/128), 256>>>(
                ph, in_proj_w + (size_t)i*2*D_INNER*D_MODEL, nullptr, pxz,
                M_TOK, 2*D_INNER, D_MODEL, D_MODEL, 0);

        // depthwise conv + silu -> u
        conv_silu_k<<<(M_TOK*D_INNER)/256, 256>>>(
            pxz, conv_w + (size_t)i*D_INNER*D_CONV, conv_b + (size_t)i*D_INNER, pu);

        // GEMM2 (split-K x4): x_dbl partials = u @ x_proj_w^T   [2048 x 96 x 2048]
        sgemm_k<64,96,16,4,6,0,true>
            <<<dim3(1, M_TOK/64, 4), 256>>>(
                pu, x_proj_w + (size_t)i*XD*D_INNER, nullptr, pxpart,
                M_TOK, XD, D_INNER, D_INNER, D_INNER/4);
        reduce4_k<<<(M_TOK*XD + 255)/256, 256>>>(pxdbl, pxpart, M_TOK*XD);

        // GEMM3: dt = softplus(dt_lo @ dt_proj_w^T + b)   [2048 x 2048 x 64], lda=96
        sgemm_k<128,128,16,8,8,1,false>
            <<<dim3(D_INNER/128, M_TOK/128), 256>>>(
                pxdbl, dt_proj_w + (size_t)i*D_INNER*DT_RANK,
                dt_proj_b + (size_t)i*D_INNER, pdt,
                M_TOK, D_INNER, DT_RANK, XD, 0);

        // selective scan + (y + D*u)*silu(z) fused -> yg
        scan_k<<<dim3(D_INNER/SC_D, BATCH), 512>>>(
            pdt, pu, pxdbl, pxz,
            A_log + (size_t)i*D_INNER*D_STATE, D_param + (size_t)i*D_INNER, pyg);

        // GEMM4: h' = silu(yg @ out_proj_w^T)   [2048 x 1024 x 2048]
        sgemm_k<128,128,16,8,8,2,false>
            <<<dim3(D_MODEL/128, M_TOK/128), 256>>>(
                pyg, out_proj_w + (size_t)i*D_MODEL*D_INNER, nullptr, h_out,
                M_TOK, D_MODEL, D_INNER, D_INNER, 0);
    }
    (void)in_sizes; (void)n_in; (void)out_size;
}